// round 6
// baseline (speedup 1.0000x reference)
#include <cuda_runtime.h>
#include <cstdint>

#define BB 8
#define CC 192
#define HH 128
#define WW 256
#define HWSZ (HH*WW)

#define HT 4
#define WT 64
#define NC 8                      // channels per stage
#define NSTAGE (CC/NC)            // 24
#define THREADS 256               // 8 warps, exact SMSP balance

#define X1_WORDS (HT*WT)          // 256
#define X2_ROWS (HT+8)            // 12
#define X2_COLS (WT+8)            // 72
#define X2_WORDS (X2_ROWS*X2_COLS)// 864
#define CH_WORDS (X1_WORDS + X2_WORDS)   // 1120
#define VECS_PER_CH (CH_WORDS/4)  // 280
#define X1_VECS (X1_WORDS/4)      // 64
#define TOT_VECS (NC*VECS_PER_CH) // 2240
#define STAGE_WORDS (NC*CH_WORDS) // 8960
#define NSLOT 9                   // ceil(2240/256)
#define SMEM_BYTES (2*STAGE_WORDS*4)   // 71680

// 16B-slot XOR swizzle (conflict-free LDS.128 for the 8-float pixel stride).
__device__ __forceinline__ int swz(int s) { return s ^ ((s >> 3) & 4); }

__device__ __forceinline__ uint32_t smem_u32(const void* p) {
    return (uint32_t)__cvta_generic_to_shared(p);
}
__device__ __forceinline__ void cp_async16(uint32_t dst, const float* src, int srcsize) {
    asm volatile("cp.async.cg.shared.global [%0], [%1], 16, %2;\n"
                 :: "r"(dst), "l"(src), "r"(srcsize));
}
__device__ __forceinline__ void cp_commit() {
    asm volatile("cp.async.commit_group;\n" ::: "memory");
}
__device__ __forceinline__ void cp_wait_all() {
    asm volatile("cp.async.wait_group 0;\n" ::: "memory");
}

// One stage (NC channels). Main i-row: 72 FMA. Slice of i-row di=+4
// (h-row wid&3, 2 px/lane): TJ=0 -> j 0..4 (10 FMA), TJ=1 -> j 5..8 (8 FMA).
// SMSP total per channel: (72+10)+(72+8) = 162 — exact balance.
template<int TJ>
__device__ __forceinline__ void do_stage(const float* __restrict__ sbuf,
    int sw1a, int sw1b,
    int sw2a, int sw2b, int sw2c, int sw2d,
    int sw3, int sw4a, int sw4b, int sw4c,
    float (&acc)[9][8], float (&acc8)[5][2]) {
    #pragma unroll
    for (int ch = 0; ch < NC; ++ch) {
        const float* p1 = sbuf + ch*CH_WORDS;
        const float* p2 = p1 + X1_WORDS;

        float a[8];
        *(float4*)(a)   = *(const float4*)(p1 + sw1a);
        *(float4*)(a+4) = *(const float4*)(p1 + sw1b);
        float v[16];
        *(float4*)(v)    = *(const float4*)(p2 + sw2a);
        *(float4*)(v+4)  = *(const float4*)(p2 + sw2b);
        *(float4*)(v+8)  = *(const float4*)(p2 + sw2c);
        *(float4*)(v+12) = *(const float4*)(p2 + sw2d);

        float a8[2];
        *(float2*)(a8) = *(const float2*)(p1 + sw3);
        float v8[6];
        *(float2*)(v8)   = *(const float2*)(p2 + sw4a);
        *(float2*)(v8+2) = *(const float2*)(p2 + sw4b);
        *(float2*)(v8+4) = *(const float2*)(p2 + sw4c);

        #pragma unroll
        for (int j = 0; j < 9; ++j)
            #pragma unroll
            for (int p = 0; p < 8; ++p)
                acc[j][p] = fmaf(a[p], v[p + 8 - j], acc[j][p]);

        #pragma unroll
        for (int jj = 0; jj < (TJ ? 4 : 5); ++jj)
            #pragma unroll
            for (int p = 0; p < 2; ++p)
                acc8[jj][p] = fmaf(a8[p], v8[p + (TJ ? 3 : 4) - jj], acc8[jj][p]);
    }
}

__global__ __launch_bounds__(THREADS, 2)
void costvol_kernel(const float* __restrict__ x1,
                    const float* __restrict__ x2,
                    float* __restrict__ out) {
    extern __shared__ __align__(16) float smem[];   // [2][STAGE_WORDS]

    const int tid  = threadIdx.x;
    const int wid  = tid >> 5;        // 0..7 -> main i-row (di = wid-4)
    const int lane = tid & 31;
    const int hl   = lane >> 3;       // main: h row
    const int g    = lane & 7;        // main: 8-px group
    const int hl2  = wid & 3;         // slice: h row
    const int tj   = wid >> 2;        // slice: 0 -> j 0..4, 1 -> j 5..8

    const int b  = blockIdx.z;
    const int h0 = blockIdx.y * HT;
    const int w0 = blockIdx.x * WT;

    // ---- staging tasks, compressed: ptr + packed meta ----
    // meta: bits 0..14 = smem word offset, bit 15 = full-size flag, -1 = skip
    const float* tptr[NSLOT];
    int tmeta[NSLOT];
    #pragma unroll
    for (int k = 0; k < NSLOT; ++k) {
        int t = tid + k * THREADS;
        if (t < TOT_VECS) {
            int ch = t / VECS_PER_CH;
            int r  = t - ch * VECS_PER_CH;
            if (r < X1_VECS) {
                int hr = r >> 4;
                int v  = r & 15;
                tptr[k]  = x1 + ((b*CC + ch)*HWSZ) + (h0 + hr)*WW + w0 + 4*v;
                tmeta[k] = (ch*CH_WORDS + swz(hr*WT + 4*v)) | 0x8000;
            } else {
                int r2  = r - X1_VECS;
                int row = r2 / 18;
                int v   = r2 - row*18;
                int gh  = h0 - 4 + row;
                int gw  = w0 - 4 + 4*v;
                int ok  = (gh >= 0) && (gh < HH) && (gw >= 0) && (gw <= WW-4);
                int ghc = min(max(gh, 0), HH-1);
                int gwc = min(max(gw, 0), WW-4);
                tptr[k]  = x2 + ((b*CC + ch)*HWSZ) + ghc*WW + gwc;
                tmeta[k] = (ch*CH_WORDS + X1_WORDS + swz(row*X2_COLS + 4*v))
                           | (ok ? 0x8000 : 0);
            }
        } else {
            tptr[k]  = x1;
            tmeta[k] = -1;
        }
    }

    const uint32_t sb0 = smem_u32(&smem[0]);
    const uint32_t sb1 = smem_u32(&smem[STAGE_WORDS]);

    // ---- compute offsets (all swizzled, hoisted) ----
    const int rr   = hl + 8 - wid;                 // main halo row
    const int s1b  = hl*WT + 8*g;
    const int s2b  = rr*X2_COLS + 8*g;
    const int sw1a = swz(s1b),     sw1b = swz(s1b + 4);
    const int sw2a = swz(s2b),     sw2b = swz(s2b + 4);
    const int sw2c = swz(s2b + 8), sw2d = swz(s2b + 12);
    const int s3   = hl2*WT + 2*lane;
    const int s4   = hl2*X2_COLS + 2*lane + (tj ? 0 : 4);
    const int sw3  = swz(s3);
    const int sw4a = swz(s4), sw4b = swz(s4 + 2), sw4c = swz(s4 + 4);

    float acc[9][8];
    #pragma unroll
    for (int j = 0; j < 9; ++j)
        #pragma unroll
        for (int p = 0; p < 8; ++p) acc[j][p] = 0.0f;
    float acc8[5][2];
    #pragma unroll
    for (int jj = 0; jj < 5; ++jj) acc8[jj][0] = acc8[jj][1] = 0.0f;

    // ---- prologue ----
    #pragma unroll
    for (int k = 0; k < NSLOT; ++k) {
        int m = tmeta[k];
        if (m >= 0)
            cp_async16(sb0 + (uint32_t)(m & 0x7fff)*4u, tptr[k], (m & 0x8000) ? 16 : 0);
    }
    cp_commit();
    cp_wait_all();
    __syncthreads();

    // ---- main loop: prefetch s+1 while computing s ----
    for (int s = 0; s < NSTAGE; ++s) {
        const int buf = s & 1;
        if (s + 1 < NSTAGE) {
            const uint32_t sbn = (buf ? sb0 : sb1);
            const int adv = (s + 1) * NC * HWSZ;
            #pragma unroll
            for (int k = 0; k < NSLOT; ++k) {
                int m = tmeta[k];
                if (m >= 0)
                    cp_async16(sbn + (uint32_t)(m & 0x7fff)*4u, tptr[k] + adv,
                               (m & 0x8000) ? 16 : 0);
            }
            cp_commit();
        }

        const float* sbuf = smem + buf*STAGE_WORDS;
        if (tj) do_stage<1>(sbuf, sw1a, sw1b, sw2a, sw2b, sw2c, sw2d,
                            sw3, sw4a, sw4b, sw4c, acc, acc8);
        else    do_stage<0>(sbuf, sw1a, sw1b, sw2a, sw2b, sw2c, sw2d,
                            sw3, sw4a, sw4b, sw4c, acc, acc8);

        cp_wait_all();
        __syncthreads();
    }

    // ---- epilogue ----
    const float inv = 1.0f / 81.0f;

    {
        const int h = h0 + hl;
        float* obase = out + (b*81)*HWSZ + h*WW + w0 + 8*g;
        #pragma unroll
        for (int j = 0; j < 9; ++j) {
            int idx = 9*wid + j + 41;
            if (idx >= 81) idx -= 81;
            float* op = obase + idx*HWSZ;
            *(float4*)(op)   = make_float4(acc[j][0]*inv, acc[j][1]*inv,
                                           acc[j][2]*inv, acc[j][3]*inv);
            *(float4*)(op+4) = make_float4(acc[j][4]*inv, acc[j][5]*inv,
                                           acc[j][6]*inv, acc[j][7]*inv);
        }
    }

    {
        const int h = h0 + hl2;
        float* obase = out + (b*81)*HWSZ + h*WW + w0 + 2*lane;
        if (tj) {
            #pragma unroll
            for (int jj = 0; jj < 4; ++jj) {
                int idx = 32 + 5 + jj;
                *(float2*)(obase + idx*HWSZ) =
                    make_float2(acc8[jj][0]*inv, acc8[jj][1]*inv);
            }
        } else {
            #pragma unroll
            for (int jj = 0; jj < 5; ++jj) {
                int idx = 32 + jj;
                *(float2*)(obase + idx*HWSZ) =
                    make_float2(acc8[jj][0]*inv, acc8[jj][1]*inv);
            }
        }
    }
}

extern "C" void kernel_launch(void* const* d_in, const int* in_sizes, int n_in,
                              void* d_out, int out_size) {
    const float* x1 = (const float*)d_in[0];
    const float* x2 = (const float*)d_in[1];
    float* out = (float*)d_out;
    cudaFuncSetAttribute(costvol_kernel,
                         cudaFuncAttributeMaxDynamicSharedMemorySize, SMEM_BYTES);
    dim3 grid(WW/WT, HH/HT, BB);   // (4, 32, 8)
    dim3 block(THREADS);
    costvol_kernel<<<grid, block, SMEM_BYTES>>>(x1, x2, out);
}

// round 7
// speedup vs baseline: 1.0763x; 1.0763x over previous
#include <cuda_runtime.h>
#include <cstdint>

#define BB 8
#define CC 192
#define HH 128
#define WW 256
#define HWSZ (HH*WW)

#define HT 4
#define WT 64
#define NC 12                     // channels per stage
#define NSTAGE (CC/NC)            // 16
#define NBUF 3                    // triple buffer, prefetch distance 2
#define THREADS 256               // 8 warps, exact SMSP balance

#define X1_WORDS (HT*WT)          // 256
#define X2_ROWS (HT+8)            // 12
#define X2_COLS (WT+8)            // 72
#define X2_WORDS (X2_ROWS*X2_COLS)// 864
#define CH_WORDS (X1_WORDS + X2_WORDS)   // 1120
#define VECS_PER_CH (CH_WORDS/4)  // 280
#define X1_VECS (X1_WORDS/4)      // 64
#define TOT_VECS (NC*VECS_PER_CH) // 3360
#define STAGE_WORDS (NC*CH_WORDS) // 13440
#define NSLOT 14                  // ceil(3360/256)
#define SMEM_BYTES (NBUF*STAGE_WORDS*4)   // 161280

// 16B-slot XOR swizzle (conflict-free LDS.128 for the 8-float pixel stride).
__device__ __forceinline__ int swz(int s) { return s ^ ((s >> 3) & 4); }

__device__ __forceinline__ uint32_t smem_u32(const void* p) {
    return (uint32_t)__cvta_generic_to_shared(p);
}
__device__ __forceinline__ void cp_async16(uint32_t dst, const float* src, int srcsize) {
    asm volatile("cp.async.cg.shared.global [%0], [%1], 16, %2;\n"
                 :: "r"(dst), "l"(src), "r"(srcsize));
}
__device__ __forceinline__ void cp_commit() {
    asm volatile("cp.async.commit_group;\n" ::: "memory");
}
template<int N>
__device__ __forceinline__ void cp_wait_group() {
    asm volatile("cp.async.wait_group %0;\n" :: "n"(N) : "memory");
}

// One stage (NC channels). Main i-row: 72 FMA. Slice of i-row di=+4
// (h-row wid&3, 2 px/lane): TJ=0 -> j 0..4 (10 FMA), TJ=1 -> j 5..8 (8 FMA).
// SMSP total per channel: (72+10)+(72+8) = 162 — exact balance.
template<int TJ>
__device__ __forceinline__ void do_stage(const float* __restrict__ sbuf,
    int sw1a, int sw1b,
    int sw2a, int sw2b, int sw2c, int sw2d,
    int sw3, int sw4a, int sw4b, int sw4c,
    float (&acc)[9][8], float (&acc8)[5][2]) {
    #pragma unroll
    for (int ch = 0; ch < NC; ++ch) {
        const float* p1 = sbuf + ch*CH_WORDS;
        const float* p2 = p1 + X1_WORDS;

        float a[8];
        *(float4*)(a)   = *(const float4*)(p1 + sw1a);
        *(float4*)(a+4) = *(const float4*)(p1 + sw1b);
        float v[16];
        *(float4*)(v)    = *(const float4*)(p2 + sw2a);
        *(float4*)(v+4)  = *(const float4*)(p2 + sw2b);
        *(float4*)(v+8)  = *(const float4*)(p2 + sw2c);
        *(float4*)(v+12) = *(const float4*)(p2 + sw2d);

        float a8[2];
        *(float2*)(a8) = *(const float2*)(p1 + sw3);
        float v8[6];
        *(float2*)(v8)   = *(const float2*)(p2 + sw4a);
        *(float2*)(v8+2) = *(const float2*)(p2 + sw4b);
        *(float2*)(v8+4) = *(const float2*)(p2 + sw4c);

        #pragma unroll
        for (int j = 0; j < 9; ++j)
            #pragma unroll
            for (int p = 0; p < 8; ++p)
                acc[j][p] = fmaf(a[p], v[p + 8 - j], acc[j][p]);

        #pragma unroll
        for (int jj = 0; jj < (TJ ? 4 : 5); ++jj)
            #pragma unroll
            for (int p = 0; p < 2; ++p)
                acc8[jj][p] = fmaf(a8[p], v8[p + (TJ ? 3 : 4) - jj], acc8[jj][p]);
    }
}

__global__ __launch_bounds__(THREADS, 1)
void costvol_kernel(const float* __restrict__ x1,
                    const float* __restrict__ x2,
                    float* __restrict__ out) {
    extern __shared__ __align__(16) float smem[];   // [NBUF][STAGE_WORDS]

    const int tid  = threadIdx.x;
    const int wid  = tid >> 5;        // 0..7 -> main i-row (di = wid-4)
    const int lane = tid & 31;
    const int hl   = lane >> 3;       // main: h row
    const int g    = lane & 7;        // main: 8-px group
    const int hl2  = wid & 3;         // slice: h row
    const int tj   = wid >> 2;        // slice: 0 -> j 0..4, 1 -> j 5..8

    const int b  = blockIdx.z;
    const int h0 = blockIdx.y * HT;
    const int w0 = blockIdx.x * WT;

    // ---- staging tasks, compressed: ptr + packed meta ----
    // meta: bits 0..14 = smem word offset, bit 15 = full-size flag, -1 = skip
    const float* tptr[NSLOT];
    int tmeta[NSLOT];
    #pragma unroll
    for (int k = 0; k < NSLOT; ++k) {
        int t = tid + k * THREADS;
        if (t < TOT_VECS) {
            int ch = t / VECS_PER_CH;
            int r  = t - ch * VECS_PER_CH;
            if (r < X1_VECS) {
                int hr = r >> 4;
                int v  = r & 15;
                tptr[k]  = x1 + ((b*CC + ch)*HWSZ) + (h0 + hr)*WW + w0 + 4*v;
                tmeta[k] = (ch*CH_WORDS + swz(hr*WT + 4*v)) | 0x8000;
            } else {
                int r2  = r - X1_VECS;
                int row = r2 / 18;
                int v   = r2 - row*18;
                int gh  = h0 - 4 + row;
                int gw  = w0 - 4 + 4*v;
                int ok  = (gh >= 0) && (gh < HH) && (gw >= 0) && (gw <= WW-4);
                int ghc = min(max(gh, 0), HH-1);
                int gwc = min(max(gw, 0), WW-4);
                tptr[k]  = x2 + ((b*CC + ch)*HWSZ) + ghc*WW + gwc;
                tmeta[k] = (ch*CH_WORDS + X1_WORDS + swz(row*X2_COLS + 4*v))
                           | (ok ? 0x8000 : 0);
            }
        } else {
            tptr[k]  = x1;
            tmeta[k] = -1;
        }
    }

    const uint32_t sbase = smem_u32(&smem[0]);

    // ---- compute offsets (all swizzled, hoisted) ----
    const int rr   = hl + 8 - wid;                 // main halo row
    const int s1b  = hl*WT + 8*g;
    const int s2b  = rr*X2_COLS + 8*g;
    const int sw1a = swz(s1b),     sw1b = swz(s1b + 4);
    const int sw2a = swz(s2b),     sw2b = swz(s2b + 4);
    const int sw2c = swz(s2b + 8), sw2d = swz(s2b + 12);
    const int s3   = hl2*WT + 2*lane;
    const int s4   = hl2*X2_COLS + 2*lane + (tj ? 0 : 4);
    const int sw3  = swz(s3);
    const int sw4a = swz(s4), sw4b = swz(s4 + 2), sw4c = swz(s4 + 4);

    float acc[9][8];
    #pragma unroll
    for (int j = 0; j < 9; ++j)
        #pragma unroll
        for (int p = 0; p < 8; ++p) acc[j][p] = 0.0f;
    float acc8[5][2];
    #pragma unroll
    for (int jj = 0; jj < 5; ++jj) acc8[jj][0] = acc8[jj][1] = 0.0f;

    // ---- prologue: issue loads for stage 0 and 1 ----
    #pragma unroll
    for (int k = 0; k < NSLOT; ++k) {
        int m = tmeta[k];
        if (m >= 0)
            cp_async16(sbase + (uint32_t)(m & 0x7fff)*4u, tptr[k], (m & 0x8000) ? 16 : 0);
    }
    cp_commit();
    {
        const uint32_t sb1 = sbase + STAGE_WORDS*4u;
        const int adv = NC * HWSZ;
        #pragma unroll
        for (int k = 0; k < NSLOT; ++k) {
            int m = tmeta[k];
            if (m >= 0)
                cp_async16(sb1 + (uint32_t)(m & 0x7fff)*4u, tptr[k] + adv,
                           (m & 0x8000) ? 16 : 0);
        }
        cp_commit();
    }

    // ---- main loop: distance-2 prefetch, triple buffer ----
    int cbuf = 0;   // buffer of stage s
    for (int s = 0; s < NSTAGE; ++s) {
        // wait for load(s): at most load(s+1) [+ load(s+2) not yet issued] pending
        if (s + 1 < NSTAGE) cp_wait_group<1>();
        else                cp_wait_group<0>();
        __syncthreads();    // all warps: load(s) visible; buf[(s+2)%3] free

        if (s + 2 < NSTAGE) {
            int pbuf = cbuf + 2; if (pbuf >= NBUF) pbuf -= NBUF;
            const uint32_t sbn = sbase + (uint32_t)pbuf*STAGE_WORDS*4u;
            const int adv = (s + 2) * NC * HWSZ;
            #pragma unroll
            for (int k = 0; k < NSLOT; ++k) {
                int m = tmeta[k];
                if (m >= 0)
                    cp_async16(sbn + (uint32_t)(m & 0x7fff)*4u, tptr[k] + adv,
                               (m & 0x8000) ? 16 : 0);
            }
            cp_commit();
        }

        const float* sbuf = smem + cbuf*STAGE_WORDS;
        if (tj) do_stage<1>(sbuf, sw1a, sw1b, sw2a, sw2b, sw2c, sw2d,
                            sw3, sw4a, sw4b, sw4c, acc, acc8);
        else    do_stage<0>(sbuf, sw1a, sw1b, sw2a, sw2b, sw2c, sw2d,
                            sw3, sw4a, sw4b, sw4c, acc, acc8);

        if (++cbuf == NBUF) cbuf = 0;
    }

    // ---- epilogue ----
    const float inv = 1.0f / 81.0f;

    {
        const int h = h0 + hl;
        float* obase = out + (b*81)*HWSZ + h*WW + w0 + 8*g;
        #pragma unroll
        for (int j = 0; j < 9; ++j) {
            int idx = 9*wid + j + 41;
            if (idx >= 81) idx -= 81;
            float* op = obase + idx*HWSZ;
            *(float4*)(op)   = make_float4(acc[j][0]*inv, acc[j][1]*inv,
                                           acc[j][2]*inv, acc[j][3]*inv);
            *(float4*)(op+4) = make_float4(acc[j][4]*inv, acc[j][5]*inv,
                                           acc[j][6]*inv, acc[j][7]*inv);
        }
    }

    {
        const int h = h0 + hl2;
        float* obase = out + (b*81)*HWSZ + h*WW + w0 + 2*lane;
        if (tj) {
            #pragma unroll
            for (int jj = 0; jj < 4; ++jj) {
                int idx = 32 + 5 + jj;
                *(float2*)(obase + idx*HWSZ) =
                    make_float2(acc8[jj][0]*inv, acc8[jj][1]*inv);
            }
        } else {
            #pragma unroll
            for (int jj = 0; jj < 5; ++jj) {
                int idx = 32 + jj;
                *(float2*)(obase + idx*HWSZ) =
                    make_float2(acc8[jj][0]*inv, acc8[jj][1]*inv);
            }
        }
    }
}

extern "C" void kernel_launch(void* const* d_in, const int* in_sizes, int n_in,
                              void* d_out, int out_size) {
    const float* x1 = (const float*)d_in[0];
    const float* x2 = (const float*)d_in[1];
    float* out = (float*)d_out;
    cudaFuncSetAttribute(costvol_kernel,
                         cudaFuncAttributeMaxDynamicSharedMemorySize, SMEM_BYTES);
    dim3 grid(WW/WT, HH/HT, BB);   // (4, 32, 8)
    dim3 block(THREADS);
    costvol_kernel<<<grid, block, SMEM_BYTES>>>(x1, x2, out);
}

// round 8
// speedup vs baseline: 1.1512x; 1.0697x over previous
#include <cuda_runtime.h>
#include <cstdint>

#define BB 8
#define CC 192
#define HH 128
#define WW 256
#define HWSZ (HH*WW)

#define HT 4
#define WT 64
#define NC 8                      // channels per stage
#define NSTAGE (CC/NC)            // 24
#define THREADS 256               // 8 warps, exact SMSP balance

#define X1_WORDS (HT*WT)          // 256
#define X2_ROWS (HT+8)            // 12
#define X2_COLS (WT+8)            // 72
#define X2_WORDS (X2_ROWS*X2_COLS)// 864
#define CH_WORDS (X1_WORDS + X2_WORDS)   // 1120
#define VECS_PER_CH (CH_WORDS/4)  // 280
#define X1_VECS (X1_WORDS/4)      // 64
#define TOT_VECS (NC*VECS_PER_CH) // 2240
#define STAGE_WORDS (NC*CH_WORDS) // 8960
#define NSLOT 9                   // ceil(2240/256)
#define SMEM_BYTES (2*STAGE_WORDS*4)   // 71680

// 16B-slot XOR swizzle (conflict-free LDS.128 for the 8-float pixel stride).
__device__ __forceinline__ int swz(int s) { return s ^ ((s >> 3) & 4); }

__device__ __forceinline__ uint32_t smem_u32(const void* p) {
    return (uint32_t)__cvta_generic_to_shared(p);
}
__device__ __forceinline__ void cp_async16(uint32_t dst, const float* src, int srcsize) {
    asm volatile("cp.async.cg.shared.global [%0], [%1], 16, %2;\n"
                 :: "r"(dst), "l"(src), "r"(srcsize));
}
__device__ __forceinline__ void cp_commit() {
    asm volatile("cp.async.commit_group;\n" ::: "memory");
}
__device__ __forceinline__ void cp_wait_all() {
    asm volatile("cp.async.wait_group 0;\n" ::: "memory");
}

// One stage (NC channels). Main i-row: 72 FMA. Slice of i-row di=+4
// (h-row wid&3, 2 px/lane): TJ=0 -> j 0..4 (10 FMA), TJ=1 -> j 5..8 (8 FMA).
// SMSP total per channel: (72+10)+(72+8) = 162 — exact balance.
// coff: channel-order rotation (anti-phases the two warps sharing an SMSP so
// their LDS bursts overlap the partner's FMA runs instead of colliding).
template<int TJ>
__device__ __forceinline__ void do_stage(const float* __restrict__ sbuf,
    int coff,
    int sw1a, int sw1b,
    int sw2a, int sw2b, int sw2c, int sw2d,
    int sw3, int sw4a, int sw4b, int sw4c,
    float (&acc)[9][8], float (&acc8)[5][2]) {
    #pragma unroll
    for (int p = 0; p < NC; ++p) {
        const int ch = (p + coff) & (NC - 1);
        const float* p1 = sbuf + ch*CH_WORDS;
        const float* p2 = p1 + X1_WORDS;

        float a[8];
        *(float4*)(a)   = *(const float4*)(p1 + sw1a);
        *(float4*)(a+4) = *(const float4*)(p1 + sw1b);
        float v[16];
        *(float4*)(v)    = *(const float4*)(p2 + sw2a);
        *(float4*)(v+4)  = *(const float4*)(p2 + sw2b);
        *(float4*)(v+8)  = *(const float4*)(p2 + sw2c);
        *(float4*)(v+12) = *(const float4*)(p2 + sw2d);

        float a8[2];
        *(float2*)(a8) = *(const float2*)(p1 + sw3);
        float v8[6];
        *(float2*)(v8)   = *(const float2*)(p2 + sw4a);
        *(float2*)(v8+2) = *(const float2*)(p2 + sw4b);
        *(float2*)(v8+4) = *(const float2*)(p2 + sw4c);

        #pragma unroll
        for (int j = 0; j < 9; ++j)
            #pragma unroll
            for (int q = 0; q < 8; ++q)
                acc[j][q] = fmaf(a[q], v[q + 8 - j], acc[j][q]);

        #pragma unroll
        for (int jj = 0; jj < (TJ ? 4 : 5); ++jj)
            #pragma unroll
            for (int q = 0; q < 2; ++q)
                acc8[jj][q] = fmaf(a8[q], v8[q + (TJ ? 3 : 4) - jj], acc8[jj][q]);
    }
}

__global__ __launch_bounds__(THREADS, 1)
void costvol_kernel(const float* __restrict__ x1,
                    const float* __restrict__ x2,
                    float* __restrict__ out) {
    extern __shared__ __align__(16) float smem[];   // [2][STAGE_WORDS]

    const int tid  = threadIdx.x;
    const int wid  = tid >> 5;        // 0..7 -> main i-row (di = wid-4)
    const int lane = tid & 31;
    const int hl   = lane >> 3;       // main: h row
    const int g    = lane & 7;        // main: 8-px group
    const int hl2  = wid & 3;         // slice: h row
    const int tj   = wid >> 2;        // slice: 0 -> j 0..4, 1 -> j 5..8
    const int coff = (wid & 1) * (NC/2);   // anti-phase channel rotation

    const int b  = blockIdx.z;
    const int h0 = blockIdx.y * HT;
    const int w0 = blockIdx.x * WT;

    // ---- staging tasks (fixed per thread; only channel advances) ----
    const float* tsrc[NSLOT];
    int tof[NSLOT];
    int tsz[NSLOT];
    #pragma unroll
    for (int k = 0; k < NSLOT; ++k) {
        int t = tid + k * THREADS;
        if (t < TOT_VECS) {
            int ch = t / VECS_PER_CH;
            int r  = t - ch * VECS_PER_CH;
            if (r < X1_VECS) {
                int hr = r >> 4;
                int v  = r & 15;
                tsrc[k] = x1 + ((b*CC + ch)*HWSZ) + (h0 + hr)*WW + w0 + 4*v;
                tof[k]  = ch*CH_WORDS + swz(hr*WT + 4*v);
                tsz[k]  = 16;
            } else {
                int r2  = r - X1_VECS;
                int row = r2 / 18;
                int v   = r2 - row*18;
                int gh  = h0 - 4 + row;
                int gw  = w0 - 4 + 4*v;
                int ok  = (gh >= 0) && (gh < HH) && (gw >= 0) && (gw <= WW-4);
                int ghc = min(max(gh, 0), HH-1);
                int gwc = min(max(gw, 0), WW-4);
                tsrc[k] = x2 + ((b*CC + ch)*HWSZ) + ghc*WW + gwc;
                tof[k]  = ch*CH_WORDS + X1_WORDS + swz(row*X2_COLS + 4*v);
                tsz[k]  = ok ? 16 : 0;
            }
        } else {
            tsrc[k] = x1;
            tof[k]  = 0;
            tsz[k]  = -1;
        }
    }

    const uint32_t sb0 = smem_u32(&smem[0]);
    const uint32_t sb1 = smem_u32(&smem[STAGE_WORDS]);

    // ---- compute offsets (all swizzled, hoisted) ----
    const int rr   = hl + 8 - wid;                 // main halo row
    const int s1b  = hl*WT + 8*g;
    const int s2b  = rr*X2_COLS + 8*g;
    const int sw1a = swz(s1b),     sw1b = swz(s1b + 4);
    const int sw2a = swz(s2b),     sw2b = swz(s2b + 4);
    const int sw2c = swz(s2b + 8), sw2d = swz(s2b + 12);
    const int s3   = hl2*WT + 2*lane;
    const int s4   = hl2*X2_COLS + 2*lane + (tj ? 0 : 4);
    const int sw3  = swz(s3);
    const int sw4a = swz(s4), sw4b = swz(s4 + 2), sw4c = swz(s4 + 4);

    float acc[9][8];
    #pragma unroll
    for (int j = 0; j < 9; ++j)
        #pragma unroll
        for (int p = 0; p < 8; ++p) acc[j][p] = 0.0f;
    float acc8[5][2];
    #pragma unroll
    for (int jj = 0; jj < 5; ++jj) acc8[jj][0] = acc8[jj][1] = 0.0f;

    // ---- prologue ----
    #pragma unroll
    for (int k = 0; k < NSLOT; ++k)
        if (tsz[k] >= 0) cp_async16(sb0 + (uint32_t)tof[k]*4u, tsrc[k], tsz[k]);
    cp_commit();
    cp_wait_all();
    __syncthreads();

    // ---- main loop: prefetch s+1 while computing s ----
    for (int s = 0; s < NSTAGE; ++s) {
        const int buf = s & 1;
        if (s + 1 < NSTAGE) {
            const uint32_t sbn = (buf ? sb0 : sb1);
            const int adv = (s + 1) * NC * HWSZ;
            #pragma unroll
            for (int k = 0; k < NSLOT; ++k)
                if (tsz[k] >= 0) cp_async16(sbn + (uint32_t)tof[k]*4u, tsrc[k] + adv, tsz[k]);
            cp_commit();
        }

        const float* sbuf = smem + buf*STAGE_WORDS;
        if (tj) do_stage<1>(sbuf, coff, sw1a, sw1b, sw2a, sw2b, sw2c, sw2d,
                            sw3, sw4a, sw4b, sw4c, acc, acc8);
        else    do_stage<0>(sbuf, coff, sw1a, sw1b, sw2a, sw2b, sw2c, sw2d,
                            sw3, sw4a, sw4b, sw4c, acc, acc8);

        cp_wait_all();
        __syncthreads();
    }

    // ---- epilogue ----
    const float inv = 1.0f / 81.0f;

    {
        const int h = h0 + hl;
        float* obase = out + (b*81)*HWSZ + h*WW + w0 + 8*g;
        #pragma unroll
        for (int j = 0; j < 9; ++j) {
            int idx = 9*wid + j + 41;
            if (idx >= 81) idx -= 81;
            float* op = obase + idx*HWSZ;
            *(float4*)(op)   = make_float4(acc[j][0]*inv, acc[j][1]*inv,
                                           acc[j][2]*inv, acc[j][3]*inv);
            *(float4*)(op+4) = make_float4(acc[j][4]*inv, acc[j][5]*inv,
                                           acc[j][6]*inv, acc[j][7]*inv);
        }
    }

    {
        const int h = h0 + hl2;
        float* obase = out + (b*81)*HWSZ + h*WW + w0 + 2*lane;
        if (tj) {
            #pragma unroll
            for (int jj = 0; jj < 4; ++jj) {
                int idx = 32 + 5 + jj;
                *(float2*)(obase + idx*HWSZ) =
                    make_float2(acc8[jj][0]*inv, acc8[jj][1]*inv);
            }
        } else {
            #pragma unroll
            for (int jj = 0; jj < 5; ++jj) {
                int idx = 32 + jj;
                *(float2*)(obase + idx*HWSZ) =
                    make_float2(acc8[jj][0]*inv, acc8[jj][1]*inv);
            }
        }
    }
}

extern "C" void kernel_launch(void* const* d_in, const int* in_sizes, int n_in,
                              void* d_out, int out_size) {
    const float* x1 = (const float*)d_in[0];
    const float* x2 = (const float*)d_in[1];
    float* out = (float*)d_out;
    cudaFuncSetAttribute(costvol_kernel,
                         cudaFuncAttributeMaxDynamicSharedMemorySize, SMEM_BYTES);
    dim3 grid(WW/WT, HH/HT, BB);   // (4, 32, 8)
    dim3 block(THREADS);
    costvol_kernel<<<grid, block, SMEM_BYTES>>>(x1, x2, out);
}